// round 7
// baseline (speedup 1.0000x reference)
#include <cuda_runtime.h>

// QCNN 8-qubit batched state simulation, round 7.
//   state = x / ||x||2  (normalizations collapse; deferred: p *= 1/s)
//   7 fused (conv+pool) 4x4 complex unitaries on wire pairs
//   output = marginal probs of wire 7
//
// Round-6 layout (kept): 16 lanes per state, 2 states per warp, 16 amps per
// thread. lane bits {3,2,1,0} = amp bits {7,6,5,3}; j bits {3,2,1,0} = amp
// bits {4,2,1,0}. Blocks (6,7),(5,7),(3,7) register-local; (2,3),(4,5),(1,3)
// mixed; (0,1) real-input lane-lane.
//
// Round-7 change: local_block16 processes its 4 amp-groups in two half-passes
// (nv[8] instead of nv[16], matrix rows loaded twice) + __launch_bounds__(256,3)
// -> regs ~106 -> ~84, 3 blocks/SM instead of 2 (occ 23.6% -> ~35%). R6 showed
// no saturated pipe and issue=48%: latency-bound at 16 warps/SM.

typedef unsigned long long u64;

// Fused block matrices, built on-device by qcnn_prep from `weights`.
//  gU[b][r][c]: .x = pack(re,re), .y = pack(im,im)  (dup'd for f32x2 FMA)
//  gUc0[r][c] : pack(re,im) of block 0 only (real-input fast path)
__device__ ulonglong2 gU[7][4][4];
__device__ u64 gUc0[4][4];

// ---------------- packed f32x2 helpers ----------------
__device__ __forceinline__ u64 pk2(float lo, float hi) {
    u64 r;
    asm("mov.b64 %0,{%1,%2};" : "=l"(r)
        : "r"(__float_as_uint(lo)), "r"(__float_as_uint(hi)));
    return r;
}
__device__ __forceinline__ void upk2(u64 v, float& lo, float& hi) {
    unsigned a, b;
    asm("mov.b64 {%0,%1},%2;" : "=r"(a), "=r"(b) : "l"(v));
    lo = __uint_as_float(a); hi = __uint_as_float(b);
}
__device__ __forceinline__ u64 ffma2(u64 a, u64 b, u64 c) {
    u64 r;
    asm("fma.rn.f32x2 %0,%1,%2,%3;" : "=l"(r) : "l"(a), "l"(b), "l"(c));
    return r;
}
__device__ __forceinline__ u64 fmul2(u64 a, u64 b) {
    u64 r;
    asm("mul.rn.f32x2 %0,%1,%2;" : "=l"(r) : "l"(a), "l"(b));
    return r;
}
// result = (accR.lo - accI.hi, accR.hi + accI.lo)
__device__ __forceinline__ u64 comb(u64 aR, u64 aI) {
    float rl, rh, il, ih;
    upk2(aR, rl, rh); upk2(aI, il, ih);
    return pk2(rl - ih, rh + il);
}

// ---------------- prep kernel: build 7 fused 4x4 unitaries ----------------
// 4-dim basis index r = 2*a + b, a = wire b1 (high), b = wire b2 (low).
__device__ __forceinline__ void rowmul(float mr[4][4], float mi[4][4], int r,
                                       float pr, float pi) {
    #pragma unroll
    for (int c = 0; c < 4; c++) {
        float a = mr[r][c], b = mi[r][c];
        mr[r][c] = a * pr - b * pi;
        mi[r][c] = a * pi + b * pr;
    }
}
__device__ __forceinline__ void rz_hi(float mr[4][4], float mi[4][4], float th) {
    float ct = cosf(0.5f * th), st = sinf(0.5f * th);
    rowmul(mr, mi, 0, ct, -st); rowmul(mr, mi, 1, ct, -st);
    rowmul(mr, mi, 2, ct,  st); rowmul(mr, mi, 3, ct,  st);
}
__device__ __forceinline__ void rz_lo(float mr[4][4], float mi[4][4], float th) {
    float ct = cosf(0.5f * th), st = sinf(0.5f * th);
    rowmul(mr, mi, 0, ct, -st); rowmul(mr, mi, 2, ct, -st);
    rowmul(mr, mi, 1, ct,  st); rowmul(mr, mi, 3, ct,  st);
}
__device__ __forceinline__ void ry2(float mr[4][4], float mi[4][4], int r0,
                                    int r1, float c, float s) {
    #pragma unroll
    for (int cc = 0; cc < 4; cc++) {
        float ar = mr[r0][cc], ai = mi[r0][cc];
        float br = mr[r1][cc], bi = mi[r1][cc];
        mr[r0][cc] = c * ar - s * br; mi[r0][cc] = c * ai - s * bi;
        mr[r1][cc] = s * ar + c * br; mi[r1][cc] = s * ai + c * bi;
    }
}
__device__ __forceinline__ void ry_lo(float mr[4][4], float mi[4][4], float th) {
    float c = cosf(0.5f * th), s = sinf(0.5f * th);
    ry2(mr, mi, 0, 1, c, s); ry2(mr, mi, 2, 3, c, s);
}
__device__ __forceinline__ void swaprows(float mr[4][4], float mi[4][4],
                                         int r0, int r1) {
    #pragma unroll
    for (int c = 0; c < 4; c++) {
        float t = mr[r0][c]; mr[r0][c] = mr[r1][c]; mr[r1][c] = t;
        t = mi[r0][c]; mi[r0][c] = mi[r1][c]; mi[r1][c] = t;
    }
}

__global__ void qcnn_prep(const float* __restrict__ w) {
    int k = threadIdx.x;
    if (k >= 7) return;
    const float PI_ = 3.14159265358979323846f;
    float mr[4][4], mi[4][4];
    #pragma unroll
    for (int r = 0; r < 4; r++)
        #pragma unroll
        for (int c = 0; c < 4; c++) {
            mr[r][c] = (r == c) ? 1.f : 0.f;
            mi[r][c] = 0.f;
        }
    const float* p = w + 6 * k;
    // conv_block
    rz_lo(mr, mi, -PI_ * 0.5f);
    swaprows(mr, mi, 1, 3);        // CNOT ctrl=b2(lo), tgt=b1(hi)
    rz_hi(mr, mi, p[0]);
    ry_lo(mr, mi, p[1]);
    swaprows(mr, mi, 2, 3);        // CNOT ctrl=b1(hi), tgt=b2(lo)
    ry_lo(mr, mi, p[2]);
    swaprows(mr, mi, 1, 3);
    rz_hi(mr, mi, PI_ * 0.5f);
    // pool_block
    rz_lo(mr, mi, -PI_ * 0.5f);
    swaprows(mr, mi, 1, 3);
    rz_hi(mr, mi, p[3]);
    ry_lo(mr, mi, p[4]);
    swaprows(mr, mi, 2, 3);
    ry_lo(mr, mi, p[5]);

    #pragma unroll
    for (int r = 0; r < 4; r++)
        #pragma unroll
        for (int c = 0; c < 4; c++) {
            gU[k][r][c].x = pk2(mr[r][c], mr[r][c]);
            gU[k][r][c].y = pk2(mi[r][c], mi[r][c]);
            if (k == 0) gUc0[r][c] = pk2(mr[r][c], mi[r][c]);
        }
}

// ---------------- main kernel block primitives ----------------
// sl = lane & 15 (sub-lane within state).
// amp(sl, j) = ((sl&0xE)<<4) | ((sl&1)<<3) | ((j&8)<<1) | (j&7)

// Block 0 (wires 0,1 -> sl masks 8,4) on a purely real state. 16 amps.
__device__ __forceinline__ void real_lane_block16(const float xr[16], u64 v[16],
                                                  int lane) {
    int r = ((lane & 8) ? 2 : 0) | ((lane & 4) ? 1 : 0);
    u64 u0 = __ldg(&gUc0[r][r]);
    u64 u1 = __ldg(&gUc0[r][r ^ 1]);
    u64 u2 = __ldg(&gUc0[r][r ^ 2]);
    u64 u3 = __ldg(&gUc0[r][r ^ 3]);
    #pragma unroll
    for (int j = 0; j < 16; j++) {
        float a0 = xr[j];
        float aB  = __shfl_xor_sync(0xffffffffu, a0, 4);   // flip wire1
        float aA  = __shfl_xor_sync(0xffffffffu, a0, 8);   // flip wire0
        float aAB = __shfl_xor_sync(0xffffffffu, a0, 12);
        u64 acc = fmul2(pk2(a0, a0), u0);
        acc = ffma2(pk2(aB, aB), u1, acc);
        acc = ffma2(pk2(aA, aA), u2, acc);
        acc = ffma2(pk2(aAB, aAB), u3, acc);
        v[j] = acc;
    }
}

// b1 (high basis bit) in the lane (MH = lane mask <16), b2 local (ML = j mask).
template <int BLK, int MH, int ML>
__device__ __forceinline__ void mixed_block16(u64 v[16], int lane) {
    int a = (lane & MH) ? 1 : 0;
    int r0 = 2 * a, r1 = 2 * a + 1, c2 = r0 ^ 2, c3 = (r0 ^ 2) + 1;
    const ulonglong2* g = &gU[BLK][0][0];
    ulonglong2 e00 = __ldg(&g[r0 * 4 + r0]), e01 = __ldg(&g[r0 * 4 + r1]);
    ulonglong2 e02 = __ldg(&g[r0 * 4 + c2]), e03 = __ldg(&g[r0 * 4 + c3]);
    ulonglong2 e10 = __ldg(&g[r1 * 4 + r0]), e11 = __ldg(&g[r1 * 4 + r1]);
    ulonglong2 e12 = __ldg(&g[r1 * 4 + c2]), e13 = __ldg(&g[r1 * 4 + c3]);
    #pragma unroll
    for (int jb = 0; jb < 16; jb++) {
        if (jb & ML) continue;
        u64 o0 = v[jb], o1 = v[jb | ML];
        u64 p0 = __shfl_xor_sync(0xffffffffu, o0, MH);
        u64 p1 = __shfl_xor_sync(0xffffffffu, o1, MH);
        u64 aR = fmul2(e00.x, o0);
        aR = ffma2(e01.x, o1, aR); aR = ffma2(e02.x, p0, aR); aR = ffma2(e03.x, p1, aR);
        u64 aI = fmul2(e00.y, o0);
        aI = ffma2(e01.y, o1, aI); aI = ffma2(e02.y, p0, aI); aI = ffma2(e03.y, p1, aI);
        u64 n0 = comb(aR, aI);
        aR = fmul2(e10.x, o0);
        aR = ffma2(e11.x, o1, aR); aR = ffma2(e12.x, p0, aR); aR = ffma2(e13.x, p1, aR);
        aI = fmul2(e10.y, o0);
        aI = ffma2(e11.y, o1, aI); aI = ffma2(e12.y, p0, aI); aI = ffma2(e13.y, p1, aI);
        v[jb] = n0;
        v[jb | ML] = comb(aR, aI);
    }
}

// Both pair bits local (MH = b1 j-mask, ML = b2 j-mask). Pure register math.
// Round-7: two half-passes over the 4 independent amp-groups so the output
// staging buffer is nv[8] (16 regs) instead of nv[16] (32 regs). Matrix rows
// are (re)loaded per half — broadcast L1-resident LDG.128, cheap.
template <int BLK, int MH, int ML>
__device__ __forceinline__ void local_block16(u64 v[16]) {
    constexpr int FREE = 0xF ^ (MH | ML);
    constexpr int FA = FREE & (-FREE);   // lower free bit
    constexpr int FB = FREE ^ FA;        // upper free bit
    const ulonglong2* g = &gU[BLK][0][0];
    #pragma unroll
    for (int half = 0; half < 2; half++) {
        const int h = half ? FB : 0;
        u64 nv[8];
        #pragma unroll
        for (int r = 0; r < 4; r++) {
            ulonglong2 e0 = __ldg(&g[r * 4 + 0]), e1 = __ldg(&g[r * 4 + 1]);
            ulonglong2 e2 = __ldg(&g[r * 4 + 2]), e3 = __ldg(&g[r * 4 + 3]);
            #pragma unroll
            for (int gi = 0; gi < 2; gi++) {
                const int f = h | (gi ? FA : 0);
                u64 a0 = v[f], a1 = v[f | ML], a2 = v[f | MH], a3 = v[f | MH | ML];
                u64 aR = fmul2(e0.x, a0);
                aR = ffma2(e1.x, a1, aR); aR = ffma2(e2.x, a2, aR); aR = ffma2(e3.x, a3, aR);
                u64 aI = fmul2(e0.y, a0);
                aI = ffma2(e1.y, a1, aI); aI = ffma2(e2.y, a2, aI); aI = ffma2(e3.y, a3, aI);
                nv[gi * 4 + r] = comb(aR, aI);
            }
        }
        #pragma unroll
        for (int gi = 0; gi < 2; gi++)
            #pragma unroll
            for (int r = 0; r < 4; r++) {
                const int f = h | (gi ? FA : 0);
                v[f | ((r & 2) ? MH : 0) | ((r & 1) ? ML : 0)] = nv[gi * 4 + r];
            }
    }
}

// ---------------- main kernel ----------------
__global__ void __launch_bounds__(256, 3)
qcnn_main(const float* __restrict__ x, float2* __restrict__ out, int nstates) {
    int wp = blockIdx.x * (blockDim.x >> 5) + (threadIdx.x >> 5);
    if (2 * wp >= nstates) return;
    int lane = threadIdx.x & 31;
    int sl = lane & 15;
    int state = 2 * wp + (lane >> 4);   // lane bit 4 selects the state

    // amp(sl, j): sl bits {3,2,1} -> amp bits {7,6,5}; sl bit 0 -> amp bit 3;
    //             j bit 3 -> amp bit 4; j bits {2,1,0} -> amp bits {2,1,0}.
    int base = ((sl & 0xE) << 4) | ((sl & 1) << 3);
    const float* xs = x + (size_t)state * 256 + base;
    float4 qa = __ldg((const float4*)(xs + 0));    // j = 0..3
    float4 qb = __ldg((const float4*)(xs + 4));    // j = 4..7
    float4 qc = __ldg((const float4*)(xs + 16));   // j = 8..11
    float4 qd = __ldg((const float4*)(xs + 20));   // j = 12..15
    float xr[16] = {qa.x, qa.y, qa.z, qa.w, qb.x, qb.y, qb.z, qb.w,
                    qc.x, qc.y, qc.z, qc.w, qd.x, qd.y, qd.z, qd.w};

    // s = ||x||^2, reduced over the 16 lanes of this state (masks < 16).
    float s = 0.f;
    #pragma unroll
    for (int j = 0; j < 16; j++) s = fmaf(xr[j], xr[j], s);
    #pragma unroll
    for (int m = 8; m; m >>= 1) s += __shfl_xor_sync(0xffffffffu, s, m);

    u64 v[16];
    real_lane_block16(xr, v, lane);    // pair (0,1): sl masks 8,4 (real input)
    mixed_block16<1, 2, 8>(v, lane);   // pair (2,3): wire2=sl mask2, wire3=j8
    mixed_block16<2, 1, 4>(v, lane);   // pair (4,5): wire4=sl mask1, wire5=j4
    local_block16<3, 2, 1>(v);         // pair (6,7): wire6=j2, wire7=j1
    mixed_block16<4, 4, 8>(v, lane);   // pair (1,3): wire1=sl mask4, wire3=j8
    local_block16<5, 4, 1>(v);         // pair (5,7): wire5=j4, wire7=j1
    local_block16<6, 8, 1>(v);         // pair (3,7): wire3=j8, wire7=j1

    // marginal over wire 7 = amp bit 0 = j bit 0
    float p0 = 0.f, p1 = 0.f;
    #pragma unroll
    for (int j = 0; j < 16; j++) {
        float re, im;
        upk2(v[j], re, im);
        float m2 = fmaf(re, re, im * im);
        if (j & 1) p1 += m2; else p0 += m2;
    }
    #pragma unroll
    for (int m = 8; m; m >>= 1) {
        p0 += __shfl_xor_sync(0xffffffffu, p0, m);
        p1 += __shfl_xor_sync(0xffffffffu, p1, m);
    }
    if (sl == 0) {
        float inv = __frcp_rn(s);
        out[state] = make_float2(p0 * inv, p1 * inv);
    }
}

extern "C" void kernel_launch(void* const* d_in, const int* in_sizes, int n_in,
                              void* d_out, int out_size) {
    int ix = (in_sizes[0] > in_sizes[1]) ? 0 : 1;   // x is the big input
    const float* x = (const float*)d_in[ix];
    const float* w = (const float*)d_in[1 - ix];
    int nstates = in_sizes[ix] / 256;

    qcnn_prep<<<1, 32>>>(w);
    int nwarps = (nstates + 1) / 2;   // 2 states per warp
    int wpb = 8;                      // 256 threads = 8 warps per block
    int blocks = (nwarps + wpb - 1) / wpb;
    qcnn_main<<<blocks, 256>>>(x, (float2*)d_out, nstates);
}

// round 8
// speedup vs baseline: 2.0138x; 2.0138x over previous
#include <cuda_runtime.h>

// QCNN 8-qubit batched state simulation, round 8.
//   state = x / ||x||2  (normalizations collapse; deferred: p *= 1/s)
//   7 fused (conv+pool) 4x4 complex unitaries on wire pairs
//   output = marginal probs of wire 7
//
// Round-6 layout (kept; R7's forced occupancy bound spilled and regressed):
// 16 lanes per state, 2 states per warp, 16 amps per thread.
//   lane bits {3,2,1,0} = amp bits {7,6,5,3} = wires {0,1,2,4}
//   j    bits {3,2,1,0} = amp bits {4,2,1,0} = wires {3,5,6,7}
// Blocks (6,7),(5,7),(3,7) register-local; (2,3),(4,5),(1,3) mixed; (0,1)
// real-input lane-lane.
//
// Round-8 change: local-block matrices (uniform, compile-time addresses) read
// from __constant__ memory -> 48 LDG.128/thread move off the L1tex/MIO pipe
// (which also carries all SHFL) onto the constant port. Lane-dependent loads
// (block 0, mixed rows) stay LDG. Matrices copied device->constant via one
// graph-capturable cudaMemcpyToSymbolAsync after qcnn_prep.

typedef unsigned long long u64;

// Fused block matrices, built on-device by qcnn_prep from `weights`.
//  gU[b][r][c]: .x = pack(re,re), .y = pack(im,im)  (dup'd for f32x2 FMA)
//  gUc0[r][c] : pack(re,im) of block 0 only (real-input fast path)
__device__ ulonglong2 gU[7][4][4];
__device__ u64 gUc0[4][4];
__constant__ ulonglong2 cU[7][4][4];   // copy of gU; used by local blocks

// ---------------- packed f32x2 helpers ----------------
__device__ __forceinline__ u64 pk2(float lo, float hi) {
    u64 r;
    asm("mov.b64 %0,{%1,%2};" : "=l"(r)
        : "r"(__float_as_uint(lo)), "r"(__float_as_uint(hi)));
    return r;
}
__device__ __forceinline__ void upk2(u64 v, float& lo, float& hi) {
    unsigned a, b;
    asm("mov.b64 {%0,%1},%2;" : "=r"(a), "=r"(b) : "l"(v));
    lo = __uint_as_float(a); hi = __uint_as_float(b);
}
__device__ __forceinline__ u64 ffma2(u64 a, u64 b, u64 c) {
    u64 r;
    asm("fma.rn.f32x2 %0,%1,%2,%3;" : "=l"(r) : "l"(a), "l"(b), "l"(c));
    return r;
}
__device__ __forceinline__ u64 fmul2(u64 a, u64 b) {
    u64 r;
    asm("mul.rn.f32x2 %0,%1,%2;" : "=l"(r) : "l"(a), "l"(b));
    return r;
}
// result = (accR.lo - accI.hi, accR.hi + accI.lo)
__device__ __forceinline__ u64 comb(u64 aR, u64 aI) {
    float rl, rh, il, ih;
    upk2(aR, rl, rh); upk2(aI, il, ih);
    return pk2(rl - ih, rh + il);
}

// ---------------- prep kernel: build 7 fused 4x4 unitaries ----------------
// 4-dim basis index r = 2*a + b, a = wire b1 (high), b = wire b2 (low).
__device__ __forceinline__ void rowmul(float mr[4][4], float mi[4][4], int r,
                                       float pr, float pi) {
    #pragma unroll
    for (int c = 0; c < 4; c++) {
        float a = mr[r][c], b = mi[r][c];
        mr[r][c] = a * pr - b * pi;
        mi[r][c] = a * pi + b * pr;
    }
}
__device__ __forceinline__ void rz_hi(float mr[4][4], float mi[4][4], float th) {
    float ct = cosf(0.5f * th), st = sinf(0.5f * th);
    rowmul(mr, mi, 0, ct, -st); rowmul(mr, mi, 1, ct, -st);
    rowmul(mr, mi, 2, ct,  st); rowmul(mr, mi, 3, ct,  st);
}
__device__ __forceinline__ void rz_lo(float mr[4][4], float mi[4][4], float th) {
    float ct = cosf(0.5f * th), st = sinf(0.5f * th);
    rowmul(mr, mi, 0, ct, -st); rowmul(mr, mi, 2, ct, -st);
    rowmul(mr, mi, 1, ct,  st); rowmul(mr, mi, 3, ct,  st);
}
__device__ __forceinline__ void ry2(float mr[4][4], float mi[4][4], int r0,
                                    int r1, float c, float s) {
    #pragma unroll
    for (int cc = 0; cc < 4; cc++) {
        float ar = mr[r0][cc], ai = mi[r0][cc];
        float br = mr[r1][cc], bi = mi[r1][cc];
        mr[r0][cc] = c * ar - s * br; mi[r0][cc] = c * ai - s * bi;
        mr[r1][cc] = s * ar + c * br; mi[r1][cc] = s * ai + c * bi;
    }
}
__device__ __forceinline__ void ry_lo(float mr[4][4], float mi[4][4], float th) {
    float c = cosf(0.5f * th), s = sinf(0.5f * th);
    ry2(mr, mi, 0, 1, c, s); ry2(mr, mi, 2, 3, c, s);
}
__device__ __forceinline__ void swaprows(float mr[4][4], float mi[4][4],
                                         int r0, int r1) {
    #pragma unroll
    for (int c = 0; c < 4; c++) {
        float t = mr[r0][c]; mr[r0][c] = mr[r1][c]; mr[r1][c] = t;
        t = mi[r0][c]; mi[r0][c] = mi[r1][c]; mi[r1][c] = t;
    }
}

__global__ void qcnn_prep(const float* __restrict__ w) {
    int k = threadIdx.x;
    if (k >= 7) return;
    const float PI_ = 3.14159265358979323846f;
    float mr[4][4], mi[4][4];
    #pragma unroll
    for (int r = 0; r < 4; r++)
        #pragma unroll
        for (int c = 0; c < 4; c++) {
            mr[r][c] = (r == c) ? 1.f : 0.f;
            mi[r][c] = 0.f;
        }
    const float* p = w + 6 * k;
    // conv_block
    rz_lo(mr, mi, -PI_ * 0.5f);
    swaprows(mr, mi, 1, 3);        // CNOT ctrl=b2(lo), tgt=b1(hi)
    rz_hi(mr, mi, p[0]);
    ry_lo(mr, mi, p[1]);
    swaprows(mr, mi, 2, 3);        // CNOT ctrl=b1(hi), tgt=b2(lo)
    ry_lo(mr, mi, p[2]);
    swaprows(mr, mi, 1, 3);
    rz_hi(mr, mi, PI_ * 0.5f);
    // pool_block
    rz_lo(mr, mi, -PI_ * 0.5f);
    swaprows(mr, mi, 1, 3);
    rz_hi(mr, mi, p[3]);
    ry_lo(mr, mi, p[4]);
    swaprows(mr, mi, 2, 3);
    ry_lo(mr, mi, p[5]);

    #pragma unroll
    for (int r = 0; r < 4; r++)
        #pragma unroll
        for (int c = 0; c < 4; c++) {
            gU[k][r][c].x = pk2(mr[r][c], mr[r][c]);
            gU[k][r][c].y = pk2(mi[r][c], mi[r][c]);
            if (k == 0) gUc0[r][c] = pk2(mr[r][c], mi[r][c]);
        }
}

// ---------------- main kernel block primitives ----------------
// sl = lane & 15 (sub-lane within state).
// amp(sl, j) = ((sl&0xE)<<4) | ((sl&1)<<3) | ((j&8)<<1) | (j&7)

// Block 0 (wires 0,1 -> sl masks 8,4) on a purely real state. 16 amps.
__device__ __forceinline__ void real_lane_block16(const float xr[16], u64 v[16],
                                                  int lane) {
    int r = ((lane & 8) ? 2 : 0) | ((lane & 4) ? 1 : 0);
    u64 u0 = __ldg(&gUc0[r][r]);
    u64 u1 = __ldg(&gUc0[r][r ^ 1]);
    u64 u2 = __ldg(&gUc0[r][r ^ 2]);
    u64 u3 = __ldg(&gUc0[r][r ^ 3]);
    #pragma unroll
    for (int j = 0; j < 16; j++) {
        float a0 = xr[j];
        float aB  = __shfl_xor_sync(0xffffffffu, a0, 4);   // flip wire1
        float aA  = __shfl_xor_sync(0xffffffffu, a0, 8);   // flip wire0
        float aAB = __shfl_xor_sync(0xffffffffu, a0, 12);
        u64 acc = fmul2(pk2(a0, a0), u0);
        acc = ffma2(pk2(aB, aB), u1, acc);
        acc = ffma2(pk2(aA, aA), u2, acc);
        acc = ffma2(pk2(aAB, aAB), u3, acc);
        v[j] = acc;
    }
}

// b1 (high basis bit) in the lane (MH = lane mask <16), b2 local (ML = j mask).
template <int BLK, int MH, int ML>
__device__ __forceinline__ void mixed_block16(u64 v[16], int lane) {
    int a = (lane & MH) ? 1 : 0;
    int r0 = 2 * a, r1 = 2 * a + 1, c2 = r0 ^ 2, c3 = (r0 ^ 2) + 1;
    const ulonglong2* g = &gU[BLK][0][0];
    ulonglong2 e00 = __ldg(&g[r0 * 4 + r0]), e01 = __ldg(&g[r0 * 4 + r1]);
    ulonglong2 e02 = __ldg(&g[r0 * 4 + c2]), e03 = __ldg(&g[r0 * 4 + c3]);
    ulonglong2 e10 = __ldg(&g[r1 * 4 + r0]), e11 = __ldg(&g[r1 * 4 + r1]);
    ulonglong2 e12 = __ldg(&g[r1 * 4 + c2]), e13 = __ldg(&g[r1 * 4 + c3]);
    #pragma unroll
    for (int jb = 0; jb < 16; jb++) {
        if (jb & ML) continue;
        u64 o0 = v[jb], o1 = v[jb | ML];
        u64 p0 = __shfl_xor_sync(0xffffffffu, o0, MH);
        u64 p1 = __shfl_xor_sync(0xffffffffu, o1, MH);
        u64 aR = fmul2(e00.x, o0);
        aR = ffma2(e01.x, o1, aR); aR = ffma2(e02.x, p0, aR); aR = ffma2(e03.x, p1, aR);
        u64 aI = fmul2(e00.y, o0);
        aI = ffma2(e01.y, o1, aI); aI = ffma2(e02.y, p0, aI); aI = ffma2(e03.y, p1, aI);
        u64 n0 = comb(aR, aI);
        aR = fmul2(e10.x, o0);
        aR = ffma2(e11.x, o1, aR); aR = ffma2(e12.x, p0, aR); aR = ffma2(e13.x, p1, aR);
        aI = fmul2(e10.y, o0);
        aI = ffma2(e11.y, o1, aI); aI = ffma2(e12.y, p0, aI); aI = ffma2(e13.y, p1, aI);
        v[jb] = n0;
        v[jb | ML] = comb(aR, aI);
    }
}

// Both pair bits local (MH = b1 j-mask, ML = b2 j-mask). Pure register math.
// Matrix rows come from __constant__ (uniform compile-time addresses -> LDC,
// off the L1tex pipe; ptxas can rematerialize near use).
template <int BLK, int MH, int ML>
__device__ __forceinline__ void local_block16(u64 v[16]) {
    u64 nv[16];
    #pragma unroll
    for (int r = 0; r < 4; r++) {
        ulonglong2 e0 = cU[BLK][r][0], e1 = cU[BLK][r][1];
        ulonglong2 e2 = cU[BLK][r][2], e3 = cU[BLK][r][3];
        #pragma unroll
        for (int f = 0; f < 16; f++) {
            if (f & (MH | ML)) continue;   // 4 free-bit groups
            u64 a0 = v[f], a1 = v[f | ML], a2 = v[f | MH], a3 = v[f | MH | ML];
            u64 aR = fmul2(e0.x, a0);
            aR = ffma2(e1.x, a1, aR); aR = ffma2(e2.x, a2, aR); aR = ffma2(e3.x, a3, aR);
            u64 aI = fmul2(e0.y, a0);
            aI = ffma2(e1.y, a1, aI); aI = ffma2(e2.y, a2, aI); aI = ffma2(e3.y, a3, aI);
            int idx = f | ((r & 2) ? MH : 0) | ((r & 1) ? ML : 0);
            nv[idx] = comb(aR, aI);
        }
    }
    #pragma unroll
    for (int j = 0; j < 16; j++) v[j] = nv[j];
}

// ---------------- main kernel ----------------
__global__ void __launch_bounds__(256)
qcnn_main(const float* __restrict__ x, float2* __restrict__ out, int nstates) {
    int wp = blockIdx.x * (blockDim.x >> 5) + (threadIdx.x >> 5);
    if (2 * wp >= nstates) return;
    int lane = threadIdx.x & 31;
    int sl = lane & 15;
    int state = 2 * wp + (lane >> 4);   // lane bit 4 selects the state

    // amp(sl, j): sl bits {3,2,1} -> amp bits {7,6,5}; sl bit 0 -> amp bit 3;
    //             j bit 3 -> amp bit 4; j bits {2,1,0} -> amp bits {2,1,0}.
    int base = ((sl & 0xE) << 4) | ((sl & 1) << 3);
    const float* xs = x + (size_t)state * 256 + base;
    float4 qa = __ldg((const float4*)(xs + 0));    // j = 0..3
    float4 qb = __ldg((const float4*)(xs + 4));    // j = 4..7
    float4 qc = __ldg((const float4*)(xs + 16));   // j = 8..11
    float4 qd = __ldg((const float4*)(xs + 20));   // j = 12..15
    float xr[16] = {qa.x, qa.y, qa.z, qa.w, qb.x, qb.y, qb.z, qb.w,
                    qc.x, qc.y, qc.z, qc.w, qd.x, qd.y, qd.z, qd.w};

    // s = ||x||^2, reduced over the 16 lanes of this state (masks < 16).
    float s = 0.f;
    #pragma unroll
    for (int j = 0; j < 16; j++) s = fmaf(xr[j], xr[j], s);
    #pragma unroll
    for (int m = 8; m; m >>= 1) s += __shfl_xor_sync(0xffffffffu, s, m);

    u64 v[16];
    real_lane_block16(xr, v, lane);    // pair (0,1): sl masks 8,4 (real input)
    mixed_block16<1, 2, 8>(v, lane);   // pair (2,3): wire2=sl mask2, wire3=j8
    mixed_block16<2, 1, 4>(v, lane);   // pair (4,5): wire4=sl mask1, wire5=j4
    local_block16<3, 2, 1>(v);         // pair (6,7): wire6=j2, wire7=j1
    mixed_block16<4, 4, 8>(v, lane);   // pair (1,3): wire1=sl mask4, wire3=j8
    local_block16<5, 4, 1>(v);         // pair (5,7): wire5=j4, wire7=j1
    local_block16<6, 8, 1>(v);         // pair (3,7): wire3=j8, wire7=j1

    // marginal over wire 7 = amp bit 0 = j bit 0
    float p0 = 0.f, p1 = 0.f;
    #pragma unroll
    for (int j = 0; j < 16; j++) {
        float re, im;
        upk2(v[j], re, im);
        float m2 = fmaf(re, re, im * im);
        if (j & 1) p1 += m2; else p0 += m2;
    }
    #pragma unroll
    for (int m = 8; m; m >>= 1) {
        p0 += __shfl_xor_sync(0xffffffffu, p0, m);
        p1 += __shfl_xor_sync(0xffffffffu, p1, m);
    }
    if (sl == 0) {
        float inv = __frcp_rn(s);
        out[state] = make_float2(p0 * inv, p1 * inv);
    }
}

extern "C" void kernel_launch(void* const* d_in, const int* in_sizes, int n_in,
                              void* d_out, int out_size) {
    int ix = (in_sizes[0] > in_sizes[1]) ? 0 : 1;   // x is the big input
    const float* x = (const float*)d_in[ix];
    const float* w = (const float*)d_in[1 - ix];
    int nstates = in_sizes[ix] / 256;

    qcnn_prep<<<1, 32>>>(w);

    // Copy fused matrices device->constant (async D2D memcpy: capturable).
    void* gU_dev = nullptr;
    cudaGetSymbolAddress(&gU_dev, gU);
    cudaMemcpyToSymbolAsync(cU, gU_dev, sizeof(cU), 0,
                            cudaMemcpyDeviceToDevice, 0);

    int nwarps = (nstates + 1) / 2;   // 2 states per warp
    int wpb = 8;                      // 256 threads = 8 warps per block
    int blocks = (nwarps + wpb - 1) / wpb;
    qcnn_main<<<blocks, 256>>>(x, (float2*)d_out, nstates);
}

// round 9
// speedup vs baseline: 2.1843x; 1.0847x over previous
#include <cuda_runtime.h>

// QCNN 8-qubit batched state simulation, round 9.
//   state = x / ||x||2  (normalizations collapse; deferred: p *= 1/s)
//   7 fused (conv+pool) 4x4 complex unitaries on wire pairs
//   output = marginal probs of wire 7
//
// Layout (round-6, kept): 16 lanes per state, 2 states per warp, 16 amps per
// thread. lane bits {3,2,1,0} = amp bits {7,6,5,3}; j bits {3,2,1,0} = amp
// bits {4,2,1,0}. Blocks (6,7),(5,7),(3,7) register-local (constant-mem
// matrices, R8); (2,3),(4,5),(1,3) mixed; (0,1) real-input lane-lane.
//
// Round-9 change: comb-free complex accumulate. Matrix element u=a+bi stored
// as .x=(a,a), .y=(-b,b); then u*z = (a,a)*(re,im) + (-b,b)*(im,re), i.e.
// 2 ffma2 per element straight into the packed result. Removes 2 FADD per
// output amp (192 fma-pipe ops/thread, ~18%) at the cost of one swapped amp
// copy per input (2 MOVs on the idle alu pipe, hoisted and reused).

typedef unsigned long long u64;

// Fused block matrices, built on-device by qcnn_prep from `weights`.
//  gU[b][r][c]: .x = pack(re,re), .y = pack(-im,im)   (comb-free form)
//  gUc0[r][c] : pack(re,im) of block 0 only (real-input fast path)
__device__ ulonglong2 gU[7][4][4];
__device__ u64 gUc0[4][4];
__constant__ ulonglong2 cU[7][4][4];   // copy of gU; used by local blocks

// ---------------- packed f32x2 helpers ----------------
__device__ __forceinline__ u64 pk2(float lo, float hi) {
    u64 r;
    asm("mov.b64 %0,{%1,%2};" : "=l"(r)
        : "r"(__float_as_uint(lo)), "r"(__float_as_uint(hi)));
    return r;
}
__device__ __forceinline__ void upk2(u64 v, float& lo, float& hi) {
    unsigned a, b;
    asm("mov.b64 {%0,%1},%2;" : "=r"(a), "=r"(b) : "l"(v));
    lo = __uint_as_float(a); hi = __uint_as_float(b);
}
// swap halves: (lo,hi) -> (hi,lo). 2 MOVs worst case, alu pipe.
__device__ __forceinline__ u64 swp(u64 v) {
    unsigned a, b;
    asm("mov.b64 {%0,%1},%2;" : "=r"(a), "=r"(b) : "l"(v));
    u64 r;
    asm("mov.b64 %0,{%1,%2};" : "=l"(r) : "r"(b), "r"(a));
    return r;
}
__device__ __forceinline__ u64 ffma2(u64 a, u64 b, u64 c) {
    u64 r;
    asm("fma.rn.f32x2 %0,%1,%2,%3;" : "=l"(r) : "l"(a), "l"(b), "l"(c));
    return r;
}
__device__ __forceinline__ u64 fmul2(u64 a, u64 b) {
    u64 r;
    asm("mul.rn.f32x2 %0,%1,%2;" : "=l"(r) : "l"(a), "l"(b));
    return r;
}

// ---------------- prep kernel: build 7 fused 4x4 unitaries ----------------
// 4-dim basis index r = 2*a + b, a = wire b1 (high), b = wire b2 (low).
__device__ __forceinline__ void rowmul(float mr[4][4], float mi[4][4], int r,
                                       float pr, float pi) {
    #pragma unroll
    for (int c = 0; c < 4; c++) {
        float a = mr[r][c], b = mi[r][c];
        mr[r][c] = a * pr - b * pi;
        mi[r][c] = a * pi + b * pr;
    }
}
__device__ __forceinline__ void rz_hi(float mr[4][4], float mi[4][4], float th) {
    float ct = cosf(0.5f * th), st = sinf(0.5f * th);
    rowmul(mr, mi, 0, ct, -st); rowmul(mr, mi, 1, ct, -st);
    rowmul(mr, mi, 2, ct,  st); rowmul(mr, mi, 3, ct,  st);
}
__device__ __forceinline__ void rz_lo(float mr[4][4], float mi[4][4], float th) {
    float ct = cosf(0.5f * th), st = sinf(0.5f * th);
    rowmul(mr, mi, 0, ct, -st); rowmul(mr, mi, 2, ct, -st);
    rowmul(mr, mi, 1, ct,  st); rowmul(mr, mi, 3, ct,  st);
}
__device__ __forceinline__ void ry2(float mr[4][4], float mi[4][4], int r0,
                                    int r1, float c, float s) {
    #pragma unroll
    for (int cc = 0; cc < 4; cc++) {
        float ar = mr[r0][cc], ai = mi[r0][cc];
        float br = mr[r1][cc], bi = mi[r1][cc];
        mr[r0][cc] = c * ar - s * br; mi[r0][cc] = c * ai - s * bi;
        mr[r1][cc] = s * ar + c * br; mi[r1][cc] = s * ai + c * bi;
    }
}
__device__ __forceinline__ void ry_lo(float mr[4][4], float mi[4][4], float th) {
    float c = cosf(0.5f * th), s = sinf(0.5f * th);
    ry2(mr, mi, 0, 1, c, s); ry2(mr, mi, 2, 3, c, s);
}
__device__ __forceinline__ void swaprows(float mr[4][4], float mi[4][4],
                                         int r0, int r1) {
    #pragma unroll
    for (int c = 0; c < 4; c++) {
        float t = mr[r0][c]; mr[r0][c] = mr[r1][c]; mr[r1][c] = t;
        t = mi[r0][c]; mi[r0][c] = mi[r1][c]; mi[r1][c] = t;
    }
}

__global__ void qcnn_prep(const float* __restrict__ w) {
    int k = threadIdx.x;
    if (k >= 7) return;
    const float PI_ = 3.14159265358979323846f;
    float mr[4][4], mi[4][4];
    #pragma unroll
    for (int r = 0; r < 4; r++)
        #pragma unroll
        for (int c = 0; c < 4; c++) {
            mr[r][c] = (r == c) ? 1.f : 0.f;
            mi[r][c] = 0.f;
        }
    const float* p = w + 6 * k;
    // conv_block
    rz_lo(mr, mi, -PI_ * 0.5f);
    swaprows(mr, mi, 1, 3);        // CNOT ctrl=b2(lo), tgt=b1(hi)
    rz_hi(mr, mi, p[0]);
    ry_lo(mr, mi, p[1]);
    swaprows(mr, mi, 2, 3);        // CNOT ctrl=b1(hi), tgt=b2(lo)
    ry_lo(mr, mi, p[2]);
    swaprows(mr, mi, 1, 3);
    rz_hi(mr, mi, PI_ * 0.5f);
    // pool_block
    rz_lo(mr, mi, -PI_ * 0.5f);
    swaprows(mr, mi, 1, 3);
    rz_hi(mr, mi, p[3]);
    ry_lo(mr, mi, p[4]);
    swaprows(mr, mi, 2, 3);
    ry_lo(mr, mi, p[5]);

    #pragma unroll
    for (int r = 0; r < 4; r++)
        #pragma unroll
        for (int c = 0; c < 4; c++) {
            gU[k][r][c].x = pk2(mr[r][c], mr[r][c]);     // (a, a)
            gU[k][r][c].y = pk2(-mi[r][c], mi[r][c]);    // (-b, b)
            if (k == 0) gUc0[r][c] = pk2(mr[r][c], mi[r][c]);
        }
}

// ---------------- main kernel block primitives ----------------
// sl = lane & 15 (sub-lane within state).
// amp(sl, j) = ((sl&0xE)<<4) | ((sl&1)<<3) | ((j&8)<<1) | (j&7)

// Block 0 (wires 0,1 -> sl masks 8,4) on a purely real state. 16 amps.
// Input real -> result is directly (x*re_u, x*im_u) packed; no comb needed.
__device__ __forceinline__ void real_lane_block16(const float xr[16], u64 v[16],
                                                  int lane) {
    int r = ((lane & 8) ? 2 : 0) | ((lane & 4) ? 1 : 0);
    u64 u0 = __ldg(&gUc0[r][r]);
    u64 u1 = __ldg(&gUc0[r][r ^ 1]);
    u64 u2 = __ldg(&gUc0[r][r ^ 2]);
    u64 u3 = __ldg(&gUc0[r][r ^ 3]);
    #pragma unroll
    for (int j = 0; j < 16; j++) {
        float a0 = xr[j];
        float aB  = __shfl_xor_sync(0xffffffffu, a0, 4);   // flip wire1
        float aA  = __shfl_xor_sync(0xffffffffu, a0, 8);   // flip wire0
        float aAB = __shfl_xor_sync(0xffffffffu, a0, 12);
        u64 acc = fmul2(pk2(a0, a0), u0);
        acc = ffma2(pk2(aB, aB), u1, acc);
        acc = ffma2(pk2(aA, aA), u2, acc);
        acc = ffma2(pk2(aAB, aAB), u3, acc);
        v[j] = acc;
    }
}

// b1 (high basis bit) in the lane (MH = lane mask <16), b2 local (ML = j mask).
// Comb-free: per group, 4 swapped inputs shared by both output rows.
template <int BLK, int MH, int ML>
__device__ __forceinline__ void mixed_block16(u64 v[16], int lane) {
    int a = (lane & MH) ? 1 : 0;
    int r0 = 2 * a, r1 = 2 * a + 1, c2 = r0 ^ 2, c3 = (r0 ^ 2) + 1;
    const ulonglong2* g = &gU[BLK][0][0];
    ulonglong2 e00 = __ldg(&g[r0 * 4 + r0]), e01 = __ldg(&g[r0 * 4 + r1]);
    ulonglong2 e02 = __ldg(&g[r0 * 4 + c2]), e03 = __ldg(&g[r0 * 4 + c3]);
    ulonglong2 e10 = __ldg(&g[r1 * 4 + r0]), e11 = __ldg(&g[r1 * 4 + r1]);
    ulonglong2 e12 = __ldg(&g[r1 * 4 + c2]), e13 = __ldg(&g[r1 * 4 + c3]);
    #pragma unroll
    for (int jb = 0; jb < 16; jb++) {
        if (jb & ML) continue;
        u64 o0 = v[jb], o1 = v[jb | ML];
        u64 p0 = __shfl_xor_sync(0xffffffffu, o0, MH);
        u64 p1 = __shfl_xor_sync(0xffffffffu, o1, MH);
        u64 wo0 = swp(o0), wo1 = swp(o1), wp0 = swp(p0), wp1 = swp(p1);
        u64 n0 = fmul2(e00.x, o0);
        n0 = ffma2(e00.y, wo0, n0);
        n0 = ffma2(e01.x, o1, n0);  n0 = ffma2(e01.y, wo1, n0);
        n0 = ffma2(e02.x, p0, n0);  n0 = ffma2(e02.y, wp0, n0);
        n0 = ffma2(e03.x, p1, n0);  n0 = ffma2(e03.y, wp1, n0);
        u64 n1 = fmul2(e10.x, o0);
        n1 = ffma2(e10.y, wo0, n1);
        n1 = ffma2(e11.x, o1, n1);  n1 = ffma2(e11.y, wo1, n1);
        n1 = ffma2(e12.x, p0, n1);  n1 = ffma2(e12.y, wp0, n1);
        n1 = ffma2(e13.x, p1, n1);  n1 = ffma2(e13.y, wp1, n1);
        v[jb] = n0;
        v[jb | ML] = n1;
    }
}

// Both pair bits local (MH = b1 j-mask, ML = b2 j-mask). Pure register math.
// Comb-free, two half-passes (2 amp-groups each): swaps hoisted once per half
// and reused across all 4 matrix rows; outputs written straight into v (the
// z/w copies hold the inputs), so no nv staging buffer.
template <int BLK, int MH, int ML>
__device__ __forceinline__ void local_block16(u64 v[16]) {
    constexpr int FREE = 0xF ^ (MH | ML);
    constexpr int FA = FREE & (-FREE);   // lower free bit
    constexpr int FB = FREE ^ FA;        // upper free bit
    #pragma unroll
    for (int half = 0; half < 2; half++) {
        const int h = half ? FB : 0;
        u64 z[8], w[8];
        #pragma unroll
        for (int gi = 0; gi < 2; gi++) {
            const int f = h | (gi ? FA : 0);
            z[gi * 4 + 0] = v[f];
            z[gi * 4 + 1] = v[f | ML];
            z[gi * 4 + 2] = v[f | MH];
            z[gi * 4 + 3] = v[f | MH | ML];
        }
        #pragma unroll
        for (int i = 0; i < 8; i++) w[i] = swp(z[i]);
        #pragma unroll
        for (int r = 0; r < 4; r++) {
            ulonglong2 e0 = cU[BLK][r][0], e1 = cU[BLK][r][1];
            ulonglong2 e2 = cU[BLK][r][2], e3 = cU[BLK][r][3];
            #pragma unroll
            for (int gi = 0; gi < 2; gi++) {
                u64 acc = fmul2(e0.x, z[gi * 4 + 0]);
                acc = ffma2(e0.y, w[gi * 4 + 0], acc);
                acc = ffma2(e1.x, z[gi * 4 + 1], acc);
                acc = ffma2(e1.y, w[gi * 4 + 1], acc);
                acc = ffma2(e2.x, z[gi * 4 + 2], acc);
                acc = ffma2(e2.y, w[gi * 4 + 2], acc);
                acc = ffma2(e3.x, z[gi * 4 + 3], acc);
                acc = ffma2(e3.y, w[gi * 4 + 3], acc);
                const int f = h | (gi ? FA : 0);
                v[f | ((r & 2) ? MH : 0) | ((r & 1) ? ML : 0)] = acc;
            }
        }
    }
}

// ---------------- main kernel ----------------
__global__ void __launch_bounds__(256)
qcnn_main(const float* __restrict__ x, float2* __restrict__ out, int nstates) {
    int wp = blockIdx.x * (blockDim.x >> 5) + (threadIdx.x >> 5);
    if (2 * wp >= nstates) return;
    int lane = threadIdx.x & 31;
    int sl = lane & 15;
    int state = 2 * wp + (lane >> 4);   // lane bit 4 selects the state

    // amp(sl, j): sl bits {3,2,1} -> amp bits {7,6,5}; sl bit 0 -> amp bit 3;
    //             j bit 3 -> amp bit 4; j bits {2,1,0} -> amp bits {2,1,0}.
    int base = ((sl & 0xE) << 4) | ((sl & 1) << 3);
    const float* xs = x + (size_t)state * 256 + base;
    float4 qa = __ldg((const float4*)(xs + 0));    // j = 0..3
    float4 qb = __ldg((const float4*)(xs + 4));    // j = 4..7
    float4 qc = __ldg((const float4*)(xs + 16));   // j = 8..11
    float4 qd = __ldg((const float4*)(xs + 20));   // j = 12..15
    float xr[16] = {qa.x, qa.y, qa.z, qa.w, qb.x, qb.y, qb.z, qb.w,
                    qc.x, qc.y, qc.z, qc.w, qd.x, qd.y, qd.z, qd.w};

    // s = ||x||^2, reduced over the 16 lanes of this state (masks < 16).
    float s = 0.f;
    #pragma unroll
    for (int j = 0; j < 16; j++) s = fmaf(xr[j], xr[j], s);
    #pragma unroll
    for (int m = 8; m; m >>= 1) s += __shfl_xor_sync(0xffffffffu, s, m);

    u64 v[16];
    real_lane_block16(xr, v, lane);    // pair (0,1): sl masks 8,4 (real input)
    mixed_block16<1, 2, 8>(v, lane);   // pair (2,3): wire2=sl mask2, wire3=j8
    mixed_block16<2, 1, 4>(v, lane);   // pair (4,5): wire4=sl mask1, wire5=j4
    local_block16<3, 2, 1>(v);         // pair (6,7): wire6=j2, wire7=j1
    mixed_block16<4, 4, 8>(v, lane);   // pair (1,3): wire1=sl mask4, wire3=j8
    local_block16<5, 4, 1>(v);         // pair (5,7): wire5=j4, wire7=j1
    local_block16<6, 8, 1>(v);         // pair (3,7): wire3=j8, wire7=j1

    // marginal over wire 7 = amp bit 0 = j bit 0
    float p0 = 0.f, p1 = 0.f;
    #pragma unroll
    for (int j = 0; j < 16; j++) {
        float re, im;
        upk2(v[j], re, im);
        float m2 = fmaf(re, re, im * im);
        if (j & 1) p1 += m2; else p0 += m2;
    }
    #pragma unroll
    for (int m = 8; m; m >>= 1) {
        p0 += __shfl_xor_sync(0xffffffffu, p0, m);
        p1 += __shfl_xor_sync(0xffffffffu, p1, m);
    }
    if (sl == 0) {
        float inv = __frcp_rn(s);
        out[state] = make_float2(p0 * inv, p1 * inv);
    }
}

extern "C" void kernel_launch(void* const* d_in, const int* in_sizes, int n_in,
                              void* d_out, int out_size) {
    int ix = (in_sizes[0] > in_sizes[1]) ? 0 : 1;   // x is the big input
    const float* x = (const float*)d_in[ix];
    const float* w = (const float*)d_in[1 - ix];
    int nstates = in_sizes[ix] / 256;

    qcnn_prep<<<1, 32>>>(w);

    // Copy fused matrices device->constant (async D2D memcpy: capturable).
    void* gU_dev = nullptr;
    cudaGetSymbolAddress(&gU_dev, gU);
    cudaMemcpyToSymbolAsync(cU, gU_dev, sizeof(cU), 0,
                            cudaMemcpyDeviceToDevice, 0);

    int nwarps = (nstates + 1) / 2;   // 2 states per warp
    int wpb = 8;                      // 256 threads = 8 warps per block
    int blocks = (nwarps + wpb - 1) / wpb;
    qcnn_main<<<blocks, 256>>>(x, (float2*)d_out, nstates);
}

// round 10
// speedup vs baseline: 2.1877x; 1.0016x over previous
#include <cuda_runtime.h>

// QCNN 8-qubit batched state simulation, round 9.
//   state = x / ||x||2  (normalizations collapse; deferred: p *= 1/s)
//   7 fused (conv+pool) 4x4 complex unitaries on wire pairs
//   output = marginal probs of wire 7
//
// Layout (round-6, kept): 16 lanes per state, 2 states per warp, 16 amps per
// thread. lane bits {3,2,1,0} = amp bits {7,6,5,3}; j bits {3,2,1,0} = amp
// bits {4,2,1,0}. Blocks (6,7),(5,7),(3,7) register-local (constant-mem
// matrices, R8); (2,3),(4,5),(1,3) mixed; (0,1) real-input lane-lane.
//
// Round-9 change: comb-free complex accumulate. Matrix element u=a+bi stored
// as .x=(a,a), .y=(-b,b); then u*z = (a,a)*(re,im) + (-b,b)*(im,re), i.e.
// 2 ffma2 per element straight into the packed result. Removes 2 FADD per
// output amp (192 fma-pipe ops/thread, ~18%) at the cost of one swapped amp
// copy per input (2 MOVs on the idle alu pipe, hoisted and reused).

typedef unsigned long long u64;

// Fused block matrices, built on-device by qcnn_prep from `weights`.
//  gU[b][r][c]: .x = pack(re,re), .y = pack(-im,im)   (comb-free form)
//  gUc0[r][c] : pack(re,im) of block 0 only (real-input fast path)
__device__ ulonglong2 gU[7][4][4];
__device__ u64 gUc0[4][4];
__constant__ ulonglong2 cU[7][4][4];   // copy of gU; used by local blocks

// ---------------- packed f32x2 helpers ----------------
__device__ __forceinline__ u64 pk2(float lo, float hi) {
    u64 r;
    asm("mov.b64 %0,{%1,%2};" : "=l"(r)
        : "r"(__float_as_uint(lo)), "r"(__float_as_uint(hi)));
    return r;
}
__device__ __forceinline__ void upk2(u64 v, float& lo, float& hi) {
    unsigned a, b;
    asm("mov.b64 {%0,%1},%2;" : "=r"(a), "=r"(b) : "l"(v));
    lo = __uint_as_float(a); hi = __uint_as_float(b);
}
// swap halves: (lo,hi) -> (hi,lo). 2 MOVs worst case, alu pipe.
__device__ __forceinline__ u64 swp(u64 v) {
    unsigned a, b;
    asm("mov.b64 {%0,%1},%2;" : "=r"(a), "=r"(b) : "l"(v));
    u64 r;
    asm("mov.b64 %0,{%1,%2};" : "=l"(r) : "r"(b), "r"(a));
    return r;
}
__device__ __forceinline__ u64 ffma2(u64 a, u64 b, u64 c) {
    u64 r;
    asm("fma.rn.f32x2 %0,%1,%2,%3;" : "=l"(r) : "l"(a), "l"(b), "l"(c));
    return r;
}
__device__ __forceinline__ u64 fmul2(u64 a, u64 b) {
    u64 r;
    asm("mul.rn.f32x2 %0,%1,%2;" : "=l"(r) : "l"(a), "l"(b));
    return r;
}

// ---------------- prep kernel: build 7 fused 4x4 unitaries ----------------
// 4-dim basis index r = 2*a + b, a = wire b1 (high), b = wire b2 (low).
__device__ __forceinline__ void rowmul(float mr[4][4], float mi[4][4], int r,
                                       float pr, float pi) {
    #pragma unroll
    for (int c = 0; c < 4; c++) {
        float a = mr[r][c], b = mi[r][c];
        mr[r][c] = a * pr - b * pi;
        mi[r][c] = a * pi + b * pr;
    }
}
__device__ __forceinline__ void rz_hi(float mr[4][4], float mi[4][4], float th) {
    float ct = cosf(0.5f * th), st = sinf(0.5f * th);
    rowmul(mr, mi, 0, ct, -st); rowmul(mr, mi, 1, ct, -st);
    rowmul(mr, mi, 2, ct,  st); rowmul(mr, mi, 3, ct,  st);
}
__device__ __forceinline__ void rz_lo(float mr[4][4], float mi[4][4], float th) {
    float ct = cosf(0.5f * th), st = sinf(0.5f * th);
    rowmul(mr, mi, 0, ct, -st); rowmul(mr, mi, 2, ct, -st);
    rowmul(mr, mi, 1, ct,  st); rowmul(mr, mi, 3, ct,  st);
}
__device__ __forceinline__ void ry2(float mr[4][4], float mi[4][4], int r0,
                                    int r1, float c, float s) {
    #pragma unroll
    for (int cc = 0; cc < 4; cc++) {
        float ar = mr[r0][cc], ai = mi[r0][cc];
        float br = mr[r1][cc], bi = mi[r1][cc];
        mr[r0][cc] = c * ar - s * br; mi[r0][cc] = c * ai - s * bi;
        mr[r1][cc] = s * ar + c * br; mi[r1][cc] = s * ai + c * bi;
    }
}
__device__ __forceinline__ void ry_lo(float mr[4][4], float mi[4][4], float th) {
    float c = cosf(0.5f * th), s = sinf(0.5f * th);
    ry2(mr, mi, 0, 1, c, s); ry2(mr, mi, 2, 3, c, s);
}
__device__ __forceinline__ void swaprows(float mr[4][4], float mi[4][4],
                                         int r0, int r1) {
    #pragma unroll
    for (int c = 0; c < 4; c++) {
        float t = mr[r0][c]; mr[r0][c] = mr[r1][c]; mr[r1][c] = t;
        t = mi[r0][c]; mi[r0][c] = mi[r1][c]; mi[r1][c] = t;
    }
}

__global__ void qcnn_prep(const float* __restrict__ w) {
    int k = threadIdx.x;
    if (k >= 7) return;
    const float PI_ = 3.14159265358979323846f;
    float mr[4][4], mi[4][4];
    #pragma unroll
    for (int r = 0; r < 4; r++)
        #pragma unroll
        for (int c = 0; c < 4; c++) {
            mr[r][c] = (r == c) ? 1.f : 0.f;
            mi[r][c] = 0.f;
        }
    const float* p = w + 6 * k;
    // conv_block
    rz_lo(mr, mi, -PI_ * 0.5f);
    swaprows(mr, mi, 1, 3);        // CNOT ctrl=b2(lo), tgt=b1(hi)
    rz_hi(mr, mi, p[0]);
    ry_lo(mr, mi, p[1]);
    swaprows(mr, mi, 2, 3);        // CNOT ctrl=b1(hi), tgt=b2(lo)
    ry_lo(mr, mi, p[2]);
    swaprows(mr, mi, 1, 3);
    rz_hi(mr, mi, PI_ * 0.5f);
    // pool_block
    rz_lo(mr, mi, -PI_ * 0.5f);
    swaprows(mr, mi, 1, 3);
    rz_hi(mr, mi, p[3]);
    ry_lo(mr, mi, p[4]);
    swaprows(mr, mi, 2, 3);
    ry_lo(mr, mi, p[5]);

    #pragma unroll
    for (int r = 0; r < 4; r++)
        #pragma unroll
        for (int c = 0; c < 4; c++) {
            gU[k][r][c].x = pk2(mr[r][c], mr[r][c]);     // (a, a)
            gU[k][r][c].y = pk2(-mi[r][c], mi[r][c]);    // (-b, b)
            if (k == 0) gUc0[r][c] = pk2(mr[r][c], mi[r][c]);
        }
}

// ---------------- main kernel block primitives ----------------
// sl = lane & 15 (sub-lane within state).
// amp(sl, j) = ((sl&0xE)<<4) | ((sl&1)<<3) | ((j&8)<<1) | (j&7)

// Block 0 (wires 0,1 -> sl masks 8,4) on a purely real state. 16 amps.
// Input real -> result is directly (x*re_u, x*im_u) packed; no comb needed.
__device__ __forceinline__ void real_lane_block16(const float xr[16], u64 v[16],
                                                  int lane) {
    int r = ((lane & 8) ? 2 : 0) | ((lane & 4) ? 1 : 0);
    u64 u0 = __ldg(&gUc0[r][r]);
    u64 u1 = __ldg(&gUc0[r][r ^ 1]);
    u64 u2 = __ldg(&gUc0[r][r ^ 2]);
    u64 u3 = __ldg(&gUc0[r][r ^ 3]);
    #pragma unroll
    for (int j = 0; j < 16; j++) {
        float a0 = xr[j];
        float aB  = __shfl_xor_sync(0xffffffffu, a0, 4);   // flip wire1
        float aA  = __shfl_xor_sync(0xffffffffu, a0, 8);   // flip wire0
        float aAB = __shfl_xor_sync(0xffffffffu, a0, 12);
        u64 acc = fmul2(pk2(a0, a0), u0);
        acc = ffma2(pk2(aB, aB), u1, acc);
        acc = ffma2(pk2(aA, aA), u2, acc);
        acc = ffma2(pk2(aAB, aAB), u3, acc);
        v[j] = acc;
    }
}

// b1 (high basis bit) in the lane (MH = lane mask <16), b2 local (ML = j mask).
// Comb-free: per group, 4 swapped inputs shared by both output rows.
template <int BLK, int MH, int ML>
__device__ __forceinline__ void mixed_block16(u64 v[16], int lane) {
    int a = (lane & MH) ? 1 : 0;
    int r0 = 2 * a, r1 = 2 * a + 1, c2 = r0 ^ 2, c3 = (r0 ^ 2) + 1;
    const ulonglong2* g = &gU[BLK][0][0];
    ulonglong2 e00 = __ldg(&g[r0 * 4 + r0]), e01 = __ldg(&g[r0 * 4 + r1]);
    ulonglong2 e02 = __ldg(&g[r0 * 4 + c2]), e03 = __ldg(&g[r0 * 4 + c3]);
    ulonglong2 e10 = __ldg(&g[r1 * 4 + r0]), e11 = __ldg(&g[r1 * 4 + r1]);
    ulonglong2 e12 = __ldg(&g[r1 * 4 + c2]), e13 = __ldg(&g[r1 * 4 + c3]);
    #pragma unroll
    for (int jb = 0; jb < 16; jb++) {
        if (jb & ML) continue;
        u64 o0 = v[jb], o1 = v[jb | ML];
        u64 p0 = __shfl_xor_sync(0xffffffffu, o0, MH);
        u64 p1 = __shfl_xor_sync(0xffffffffu, o1, MH);
        u64 wo0 = swp(o0), wo1 = swp(o1), wp0 = swp(p0), wp1 = swp(p1);
        u64 n0 = fmul2(e00.x, o0);
        n0 = ffma2(e00.y, wo0, n0);
        n0 = ffma2(e01.x, o1, n0);  n0 = ffma2(e01.y, wo1, n0);
        n0 = ffma2(e02.x, p0, n0);  n0 = ffma2(e02.y, wp0, n0);
        n0 = ffma2(e03.x, p1, n0);  n0 = ffma2(e03.y, wp1, n0);
        u64 n1 = fmul2(e10.x, o0);
        n1 = ffma2(e10.y, wo0, n1);
        n1 = ffma2(e11.x, o1, n1);  n1 = ffma2(e11.y, wo1, n1);
        n1 = ffma2(e12.x, p0, n1);  n1 = ffma2(e12.y, wp0, n1);
        n1 = ffma2(e13.x, p1, n1);  n1 = ffma2(e13.y, wp1, n1);
        v[jb] = n0;
        v[jb | ML] = n1;
    }
}

// Both pair bits local (MH = b1 j-mask, ML = b2 j-mask). Pure register math.
// Comb-free, two half-passes (2 amp-groups each): swaps hoisted once per half
// and reused across all 4 matrix rows; outputs written straight into v (the
// z/w copies hold the inputs), so no nv staging buffer.
template <int BLK, int MH, int ML>
__device__ __forceinline__ void local_block16(u64 v[16]) {
    constexpr int FREE = 0xF ^ (MH | ML);
    constexpr int FA = FREE & (-FREE);   // lower free bit
    constexpr int FB = FREE ^ FA;        // upper free bit
    #pragma unroll
    for (int half = 0; half < 2; half++) {
        const int h = half ? FB : 0;
        u64 z[8], w[8];
        #pragma unroll
        for (int gi = 0; gi < 2; gi++) {
            const int f = h | (gi ? FA : 0);
            z[gi * 4 + 0] = v[f];
            z[gi * 4 + 1] = v[f | ML];
            z[gi * 4 + 2] = v[f | MH];
            z[gi * 4 + 3] = v[f | MH | ML];
        }
        #pragma unroll
        for (int i = 0; i < 8; i++) w[i] = swp(z[i]);
        #pragma unroll
        for (int r = 0; r < 4; r++) {
            ulonglong2 e0 = cU[BLK][r][0], e1 = cU[BLK][r][1];
            ulonglong2 e2 = cU[BLK][r][2], e3 = cU[BLK][r][3];
            #pragma unroll
            for (int gi = 0; gi < 2; gi++) {
                u64 acc = fmul2(e0.x, z[gi * 4 + 0]);
                acc = ffma2(e0.y, w[gi * 4 + 0], acc);
                acc = ffma2(e1.x, z[gi * 4 + 1], acc);
                acc = ffma2(e1.y, w[gi * 4 + 1], acc);
                acc = ffma2(e2.x, z[gi * 4 + 2], acc);
                acc = ffma2(e2.y, w[gi * 4 + 2], acc);
                acc = ffma2(e3.x, z[gi * 4 + 3], acc);
                acc = ffma2(e3.y, w[gi * 4 + 3], acc);
                const int f = h | (gi ? FA : 0);
                v[f | ((r & 2) ? MH : 0) | ((r & 1) ? ML : 0)] = acc;
            }
        }
    }
}

// ---------------- main kernel ----------------
__global__ void __launch_bounds__(256)
qcnn_main(const float* __restrict__ x, float2* __restrict__ out, int nstates) {
    int wp = blockIdx.x * (blockDim.x >> 5) + (threadIdx.x >> 5);
    if (2 * wp >= nstates) return;
    int lane = threadIdx.x & 31;
    int sl = lane & 15;
    int state = 2 * wp + (lane >> 4);   // lane bit 4 selects the state

    // amp(sl, j): sl bits {3,2,1} -> amp bits {7,6,5}; sl bit 0 -> amp bit 3;
    //             j bit 3 -> amp bit 4; j bits {2,1,0} -> amp bits {2,1,0}.
    int base = ((sl & 0xE) << 4) | ((sl & 1) << 3);
    const float* xs = x + (size_t)state * 256 + base;
    float4 qa = __ldg((const float4*)(xs + 0));    // j = 0..3
    float4 qb = __ldg((const float4*)(xs + 4));    // j = 4..7
    float4 qc = __ldg((const float4*)(xs + 16));   // j = 8..11
    float4 qd = __ldg((const float4*)(xs + 20));   // j = 12..15
    float xr[16] = {qa.x, qa.y, qa.z, qa.w, qb.x, qb.y, qb.z, qb.w,
                    qc.x, qc.y, qc.z, qc.w, qd.x, qd.y, qd.z, qd.w};

    // s = ||x||^2, reduced over the 16 lanes of this state (masks < 16).
    float s = 0.f;
    #pragma unroll
    for (int j = 0; j < 16; j++) s = fmaf(xr[j], xr[j], s);
    #pragma unroll
    for (int m = 8; m; m >>= 1) s += __shfl_xor_sync(0xffffffffu, s, m);

    u64 v[16];
    real_lane_block16(xr, v, lane);    // pair (0,1): sl masks 8,4 (real input)
    mixed_block16<1, 2, 8>(v, lane);   // pair (2,3): wire2=sl mask2, wire3=j8
    mixed_block16<2, 1, 4>(v, lane);   // pair (4,5): wire4=sl mask1, wire5=j4
    local_block16<3, 2, 1>(v);         // pair (6,7): wire6=j2, wire7=j1
    mixed_block16<4, 4, 8>(v, lane);   // pair (1,3): wire1=sl mask4, wire3=j8
    local_block16<5, 4, 1>(v);         // pair (5,7): wire5=j4, wire7=j1
    local_block16<6, 8, 1>(v);         // pair (3,7): wire3=j8, wire7=j1

    // marginal over wire 7 = amp bit 0 = j bit 0
    float p0 = 0.f, p1 = 0.f;
    #pragma unroll
    for (int j = 0; j < 16; j++) {
        float re, im;
        upk2(v[j], re, im);
        float m2 = fmaf(re, re, im * im);
        if (j & 1) p1 += m2; else p0 += m2;
    }
    #pragma unroll
    for (int m = 8; m; m >>= 1) {
        p0 += __shfl_xor_sync(0xffffffffu, p0, m);
        p1 += __shfl_xor_sync(0xffffffffu, p1, m);
    }
    if (sl == 0) {
        float inv = __frcp_rn(s);
        out[state] = make_float2(p0 * inv, p1 * inv);
    }
}

extern "C" void kernel_launch(void* const* d_in, const int* in_sizes, int n_in,
                              void* d_out, int out_size) {
    int ix = (in_sizes[0] > in_sizes[1]) ? 0 : 1;   // x is the big input
    const float* x = (const float*)d_in[ix];
    const float* w = (const float*)d_in[1 - ix];
    int nstates = in_sizes[ix] / 256;

    qcnn_prep<<<1, 32>>>(w);

    // Copy fused matrices device->constant (async D2D memcpy: capturable).
    void* gU_dev = nullptr;
    cudaGetSymbolAddress(&gU_dev, gU);
    cudaMemcpyToSymbolAsync(cU, gU_dev, sizeof(cU), 0,
                            cudaMemcpyDeviceToDevice, 0);

    int nwarps = (nstates + 1) / 2;   // 2 states per warp
    int wpb = 8;                      // 256 threads = 8 warps per block
    int blocks = (nwarps + wpb - 1) / wpb;
    qcnn_main<<<blocks, 256>>>(x, (float2*)d_out, nstates);
}